// round 9
// baseline (speedup 1.0000x reference)
#include <cuda_runtime.h>
#include <cuda_fp16.h>
#include <cstdint>

// ---------------------------------------------------------------------------
// GraphDecoder decode-step — fp16 mma.sync (m16n8k16), ldmatrix + SW128 smem,
// 3-stage cp.async pipeline, wave-pooled scheduling.
// (tcgen05 not compilable under this harness: PTX target compute_103 lacks
//  the 'a' feature set — verified R4.)
//
// Launches:
//   P1: fused prepass (fp16 rounding, ctx gather, boh pad)
//   P2: batched weight transposes (5 matrices -> [N][Kpad] fp16)
//   P3: W2 block-diag assembly + bias concat
//   A : pool( K1 hist=relu([znode|boh8]@wbond)      , KF slice 0 )
//   B : pool( K2 cur =relu([hist|aoh]@rbond)        , KF slice 1 )
//   C : pool( K5 h_b =relu([gvec|cur|znode|ctx]@bond), KF slice 2 )
//   D : K6 out=[hta|h_b]@W2t+b2  (K=1536, N=69, f32)
//   KF: hta = relu([gvec|xnode|ctx] @ [topo|atom]), K=1152, N=1024
// ---------------------------------------------------------------------------

#define M_ROWS 32768
#define BM 128
#define BN 128
#define BK 64
#define ATILE_B (BM * BK * 2)            // 16384 B
#define STAGE_B (2 * ATILE_B)            // 32768 B
#define NSTAGE 3
#define SMEM_BYTES (NSTAGE * STAGE_B)    // 98304 B

struct SegH { const __half* ptr; int width; };
struct SegsH { SegH s[4]; };

struct GemmDesc {
    SegsH segs;
    const __half* Bt;
    const float*  bias;
    void*         C;
    int ldb, ldc, N, nk, gx, my0, relu, outh;
};

// ----- fp16 scratch -----
__device__ __half g_gvec_h [(size_t)M_ROWS * 512];
__device__ __half g_xnode_h[(size_t)M_ROWS * 512];
__device__ __half g_znode_h[(size_t)M_ROWS * 512];
__device__ __half g_ctx_h  [(size_t)M_ROWS * 128];
__device__ __half g_aoh_h  [(size_t)M_ROWS * 64];
__device__ __half g_boh_h  [(size_t)M_ROWS * 8];
__device__ __half g_hist_h [(size_t)M_ROWS * 512];
__device__ __half g_cur_h  [(size_t)M_ROWS * 512];
__device__ __half g_hta_h  [(size_t)M_ROWS * 1024];
__device__ __half g_hb_h   [(size_t)M_ROWS * 512];
__device__ __half g_wt_ta   [1024 * 1152];
__device__ __half g_wt_bond [512 * 1664];
__device__ __half g_wt_rbond[512 * 576];
__device__ __half g_wt_wbond[512 * 576];
__device__ __half g_w2t     [128 * 1536];
__device__ float  g_b_ta[1024];
__device__ float  g_b2[72];

// ---------------------------------------------------------------------------
// P1: fused prepass — gvec | xnode | znode | aoh | boh-pad | ctx-gather
// ---------------------------------------------------------------------------
__global__ void prepass_main(const float* __restrict__ gvec,
                             const float* __restrict__ xnode,
                             const float* __restrict__ znode,
                             const float* __restrict__ aoh,
                             const float* __restrict__ boh,
                             const float* __restrict__ src,
                             const int* __restrict__ idx,
                             __half* __restrict__ gvh, __half* __restrict__ xnh,
                             __half* __restrict__ znh, __half* __restrict__ aohh,
                             __half* __restrict__ bohh, __half* __restrict__ ctxh)
{
    const int n512 = M_ROWS * 128;
    const int nA   = M_ROWS * 16;
    const int nB   = M_ROWS * 2;
    const int nC   = M_ROWS * 32;
    int i = blockIdx.x * blockDim.x + threadIdx.x;
    if (i >= 3 * n512 + nA + nB + nC) return;

    const float* in;
    __half* out;
    int j;
    if (i < n512)               { in = gvec;  out = gvh;  j = i; }
    else if (i < 2 * n512)      { in = xnode; out = xnh;  j = i - n512; }
    else if (i < 3 * n512)      { in = znode; out = znh;  j = i - 2 * n512; }
    else if (i < 3 * n512 + nA) { in = aoh;   out = aohh; j = i - 3 * n512; }
    else if (i < 3 * n512 + nA + nB) {
        j = i - 3 * n512 - nA;
        int m = j >> 1, g = j & 1;
        __half2 h0, h1;
        if (g == 0) {
            float4 v = *reinterpret_cast<const float4*>(boh + (size_t)m * 4);
            h0 = __floats2half2_rn(v.x, v.y);
            h1 = __floats2half2_rn(v.z, v.w);
        } else {
            h0 = __floats2half2_rn(0.f, 0.f);
            h1 = h0;
        }
        __half* o = bohh + (size_t)m * 8 + g * 4;
        *reinterpret_cast<__half2*>(o)     = h0;
        *reinterpret_cast<__half2*>(o + 2) = h1;
        return;
    } else {
        j = i - 3 * n512 - nA - nB;
        int m = j >> 5;
        int c = (j & 31) * 4;
        float4 v = *reinterpret_cast<const float4*>(src + (size_t)idx[m] * 128 + c);
        __half* o = ctxh + (size_t)m * 128 + c;
        *reinterpret_cast<__half2*>(o)     = __floats2half2_rn(v.x, v.y);
        *reinterpret_cast<__half2*>(o + 2) = __floats2half2_rn(v.z, v.w);
        return;
    }
    float4 v = *reinterpret_cast<const float4*>(in + (size_t)j * 4);
    *reinterpret_cast<__half2*>(out + (size_t)j * 4)     = __floats2half2_rn(v.x, v.y);
    *reinterpret_cast<__half2*>(out + (size_t)j * 4 + 2) = __floats2half2_rn(v.z, v.w);
}

// ---------------------------------------------------------------------------
// P2: batched transposes.  w [Kin][N] f32 -> wt [N][Kpad] fp16.
// ---------------------------------------------------------------------------
struct TD { const float* w; __half* wt; int Kin, Kpad, N, tiles, kTiles; };

__global__ void transpose_all(TD t0, TD t1, TD t2, TD t3, TD t4)
{
    __shared__ float t[32][33];
    int id = blockIdx.x;
    TD td;
    if (id < t0.tiles) td = t0;
    else { id -= t0.tiles;
    if (id < t1.tiles) td = t1;
    else { id -= t1.tiles;
    if (id < t2.tiles) td = t2;
    else { id -= t2.tiles;
    if (id < t3.tiles) td = t3;
    else { id -= t3.tiles; td = t4; } } } }

    int kb = (id % td.kTiles) * 32;
    int nb = (id / td.kTiles) * 32;
    int x = threadIdx.x, y = threadIdx.y;  // (32, 8)
#pragma unroll
    for (int dy = 0; dy < 32; dy += 8) {
        int k = kb + y + dy, n = nb + x;
        t[y + dy][x] = (k < td.Kin && n < td.N) ? td.w[(size_t)k * td.N + n] : 0.0f;
    }
    __syncthreads();
#pragma unroll
    for (int dy = 0; dy < 32; dy += 8) {
        int n = nb + y + dy, k = kb + x;
        if (n < td.N && k < td.Kpad)
            td.wt[(size_t)n * td.Kpad + k] = __float2half_rn(t[x][y + dy]);
    }
}

// ---------------------------------------------------------------------------
// P3: W2 block-diag [128 x 1536] + biases
// ---------------------------------------------------------------------------
__global__ void build_w2t(const float* __restrict__ tw2, const float* __restrict__ tb2,
                          const float* __restrict__ aw2, const float* __restrict__ ab2,
                          const float* __restrict__ bw2, const float* __restrict__ bb2,
                          const float* __restrict__ tb1, const float* __restrict__ ab1)
{
    int i = blockIdx.x * blockDim.x + threadIdx.x;
    if (i < 128 * 1536) {
        int n = i / 1536, k = i - n * 1536;
        float v = 0.0f;
        if (n == 0) {
            if (k < 512) v = tw2[k];
        } else if (n < 65) {
            if (k >= 512 && k < 1024) v = aw2[(k - 512) * 64 + (n - 1)];
        } else if (n < 69) {
            if (k >= 1024) v = bw2[(k - 1024) * 4 + (n - 65)];
        }
        g_w2t[i] = __float2half_rn(v);
    }
    if (i < 72) {
        float b = 0.0f;
        if (i == 0)      b = tb2[0];
        else if (i < 65) b = ab2[i - 1];
        else if (i < 69) b = bb2[i - 65];
        g_b2[i] = b;
    }
    if (i < 1024) g_b_ta[i] = (i < 512) ? tb1[i] : ab1[i - 512];
}

// ---------------------------------------------------------------------------
__device__ __forceinline__ void cp_async16(uint32_t smem_dst, const void* gsrc, int src_bytes)
{
    asm volatile("cp.async.cg.shared.global [%0], [%1], 16, %2;\n"
                 :: "r"(smem_dst), "l"(gsrc), "r"(src_bytes));
}
__device__ __forceinline__ void mma_f16(float* c, const uint32_t* a, const uint32_t* b)
{
    asm volatile(
        "mma.sync.aligned.m16n8k16.row.col.f32.f16.f16.f32 "
        "{%0,%1,%2,%3}, {%4,%5,%6,%7}, {%8,%9}, {%0,%1,%2,%3};"
        : "+f"(c[0]), "+f"(c[1]), "+f"(c[2]), "+f"(c[3])
        : "r"(a[0]), "r"(a[1]), "r"(a[2]), "r"(a[3]), "r"(b[0]), "r"(b[1]));
}
__device__ __forceinline__ void ldsm_x4(uint32_t& r0, uint32_t& r1, uint32_t& r2,
                                        uint32_t& r3, uint32_t addr)
{
    asm volatile("ldmatrix.sync.aligned.m8n8.x4.shared.b16 {%0,%1,%2,%3}, [%4];"
                 : "=r"(r0), "=r"(r1), "=r"(r2), "=r"(r3) : "r"(addr));
}
__device__ __forceinline__ uint32_t swz(uint32_t row, uint32_t kbyte)
{
    return row * 128u + (kbyte ^ ((row & 7u) * 16u));
}

// ---------------------------------------------------------------------------
// Pooled segmented-A fp16 GEMM: two problems per launch, selected by CTA id.
// ---------------------------------------------------------------------------
__global__ __launch_bounds__(256, 2)
void mma_pool(GemmDesc d0, GemmDesc d1, int n0)
{
    extern __shared__ char sm[];
    const uint32_t sbase = (uint32_t)__cvta_generic_to_shared(sm);

    const bool first = ((int)blockIdx.x < n0);
    GemmDesc d = first ? d0 : d1;
    const int local = (int)blockIdx.x - (first ? 0 : n0);

    const int bn = (local % d.gx) * BN;
    const int bm = (local / d.gx + d.my0) * BM;

    const int tid  = threadIdx.x;
    const int lane = tid & 31;
    const int warp = tid >> 5;
    const int wm   = warp >> 2;
    const int wn   = warp & 3;

    const int arow = tid >> 3;
    const int ac8  = tid & 7;

    const int nk = d.nk;
    const bool wact = (bn + wn * 32) < ((d.N + 7) & ~7);

    const uint32_t a_row_l = (lane & 7) + ((lane >> 3) & 1) * 8;
    const uint32_t a_kx    = ((lane >> 4) & 1) * 16;
    const uint32_t b_row_l = (lane & 7) + ((lane >> 4) & 1) * 8;
    const uint32_t b_kx    = ((lane >> 3) & 1) * 16;

    float acc[4][4][4];
#pragma unroll
    for (int mt = 0; mt < 4; ++mt)
#pragma unroll
        for (int nt = 0; nt < 4; ++nt)
#pragma unroll
            for (int i = 0; i < 4; ++i) acc[mt][nt][i] = 0.0f;

    auto load_tile = [&](int kt, int buf) {
        const uint32_t Aoff = sbase + buf * STAGE_B;
        const uint32_t Boff = Aoff + ATILE_B;
        const int k0 = kt * BK;
        const int col = k0 + ac8 * 8;
        const __half* sptr = nullptr;
        int swid = 0, cloc = 0;
        bool valid = false;
        int cc = col;
#pragma unroll
        for (int s = 0; s < 4; ++s) {
            if (cc >= 0 && cc < d.segs.s[s].width) {
                sptr = d.segs.s[s].ptr; swid = d.segs.s[s].width;
                cloc = cc; valid = true;
            }
            cc -= d.segs.s[s].width;
        }
#pragma unroll
        for (int p = 0; p < 4; ++p) {
            const uint32_t row = arow + 32 * p;
            const void* src = valid
                ? (const void*)(sptr + (size_t)(bm + row) * swid + cloc)
                : (const void*)d.bias;
            cp_async16(Aoff + swz(row, ac8 * 16), src, valid ? 16 : 0);
        }
#pragma unroll
        for (int p = 0; p < 4; ++p) {
            const uint32_t row = arow + 32 * p;
            const void* src = d.Bt + (size_t)(bn + row) * d.ldb + k0 + ac8 * 8;
            cp_async16(Boff + swz(row, ac8 * 16), src, 16);
        }
        asm volatile("cp.async.commit_group;\n" ::);
    };

    load_tile(0, 0);
    if (nk > 1) load_tile(1, 1);

    for (int kt = 0; kt < nk; ++kt) {
        const int buf = kt % NSTAGE;
        if (kt + 2 < nk) {
            load_tile(kt + 2, (kt + 2) % NSTAGE);
            asm volatile("cp.async.wait_group 2;\n" ::);
        } else if (kt + 1 < nk) {
            asm volatile("cp.async.wait_group 1;\n" ::);
        } else {
            asm volatile("cp.async.wait_group 0;\n" ::);
        }
        __syncthreads();

        const uint32_t Aoff = sbase + buf * STAGE_B;
        const uint32_t Boff = Aoff + ATILE_B;

        if (wact) {
#pragma unroll
            for (int s = 0; s < BK / 16; ++s) {
                const uint32_t ka = s * 32 + a_kx;
                const uint32_t kb = s * 32 + b_kx;
                uint32_t a[4][4], b[2][4];
#pragma unroll
                for (int mt = 0; mt < 4; ++mt) {
                    const uint32_t row = wm * 64 + mt * 16 + a_row_l;
                    ldsm_x4(a[mt][0], a[mt][1], a[mt][2], a[mt][3], Aoff + swz(row, ka));
                }
#pragma unroll
                for (int np = 0; np < 2; ++np) {
                    const uint32_t row = wn * 32 + np * 16 + b_row_l;
                    ldsm_x4(b[np][0], b[np][1], b[np][2], b[np][3], Boff + swz(row, kb));
                }
#pragma unroll
                for (int mt = 0; mt < 4; ++mt)
#pragma unroll
                    for (int nt = 0; nt < 4; ++nt)
                        mma_f16(acc[mt][nt], a[mt], &b[nt >> 1][(nt & 1) * 2]);
            }
        }
        __syncthreads();
    }

    // ---- epilogue ----
#pragma unroll
    for (int mt = 0; mt < 4; ++mt) {
        const int r0 = bm + wm * 64 + mt * 16 + (lane >> 2);
#pragma unroll
        for (int nt = 0; nt < 4; ++nt) {
            const int c0 = bn + wn * 32 + nt * 8 + (lane & 3) * 2;
            float bv0 = (c0     < d.N) ? d.bias[c0]     : 0.0f;
            float bv1 = (c0 + 1 < d.N) ? d.bias[c0 + 1] : 0.0f;
            float v00 = acc[mt][nt][0] + bv0;
            float v01 = acc[mt][nt][1] + bv1;
            float v10 = acc[mt][nt][2] + bv0;
            float v11 = acc[mt][nt][3] + bv1;
            if (d.relu) {
                v00 = fmaxf(v00, 0.0f); v01 = fmaxf(v01, 0.0f);
                v10 = fmaxf(v10, 0.0f); v11 = fmaxf(v11, 0.0f);
            }
            if (d.outh) {
                __half* C = (__half*)d.C;
                *reinterpret_cast<__half2*>(C + (size_t)r0 * d.ldc + c0)
                    = __floats2half2_rn(v00, v01);
                *reinterpret_cast<__half2*>(C + (size_t)(r0 + 8) * d.ldc + c0)
                    = __floats2half2_rn(v10, v11);
            } else {
                float* C = (float*)d.C;
                if (c0 < d.N) {
                    C[(size_t)r0 * d.ldc + c0]       = v00;
                    C[(size_t)(r0 + 8) * d.ldc + c0] = v10;
                }
                if (c0 + 1 < d.N) {
                    C[(size_t)r0 * d.ldc + c0 + 1]       = v01;
                    C[(size_t)(r0 + 8) * d.ldc + c0 + 1] = v11;
                }
            }
        }
    }
}

// ---------------------------------------------------------------------------
extern "C" void kernel_launch(void* const* d_in, const int* in_sizes, int n_in,
                              void* d_out, int out_size)
{
    (void)in_sizes; (void)n_in; (void)out_size;

    const float* src_graph_vecs = (const float*)d_in[0];
    const float* gvec           = (const float*)d_in[1];
    const float* xnode          = (const float*)d_in[2];
    const float* znode          = (const float*)d_in[3];
    const float* atom_onehot    = (const float*)d_in[4];
    const float* bond_onehot    = (const float*)d_in[5];
    const float* topo_w1        = (const float*)d_in[6];
    const float* topo_b1        = (const float*)d_in[7];
    const float* topo_w2        = (const float*)d_in[8];
    const float* topo_b2        = (const float*)d_in[9];
    const float* atom_w1        = (const float*)d_in[10];
    const float* atom_b1        = (const float*)d_in[11];
    const float* atom_w2        = (const float*)d_in[12];
    const float* atom_b2        = (const float*)d_in[13];
    const float* bond_w1        = (const float*)d_in[14];
    const float* bond_b1        = (const float*)d_in[15];
    const float* bond_w2        = (const float*)d_in[16];
    const float* bond_b2        = (const float*)d_in[17];
    const float* rbond_w        = (const float*)d_in[18];
    const float* rbond_b        = (const float*)d_in[19];
    const float* wbond_w        = (const float*)d_in[20];
    const float* wbond_b        = (const float*)d_in[21];
    const int*   batch_idx      = (const int*)d_in[22];
    float*       out            = (float*)d_out;

    __half *gvh, *xnh, *znh, *ctxh, *aohh, *bohh;
    __half *histh, *curh, *htah, *hbh;
    __half *wtTA, *wtB, *wtR, *wtW, *w2t;
    float  *b2, *bta;
    cudaGetSymbolAddress((void**)&gvh,   g_gvec_h);
    cudaGetSymbolAddress((void**)&xnh,   g_xnode_h);
    cudaGetSymbolAddress((void**)&znh,   g_znode_h);
    cudaGetSymbolAddress((void**)&ctxh,  g_ctx_h);
    cudaGetSymbolAddress((void**)&aohh,  g_aoh_h);
    cudaGetSymbolAddress((void**)&bohh,  g_boh_h);
    cudaGetSymbolAddress((void**)&histh, g_hist_h);
    cudaGetSymbolAddress((void**)&curh,  g_cur_h);
    cudaGetSymbolAddress((void**)&htah,  g_hta_h);
    cudaGetSymbolAddress((void**)&hbh,   g_hb_h);
    cudaGetSymbolAddress((void**)&wtTA,  g_wt_ta);
    cudaGetSymbolAddress((void**)&wtB,   g_wt_bond);
    cudaGetSymbolAddress((void**)&wtR,   g_wt_rbond);
    cudaGetSymbolAddress((void**)&wtW,   g_wt_wbond);
    cudaGetSymbolAddress((void**)&w2t,   g_w2t);
    cudaGetSymbolAddress((void**)&b2,    g_b2);
    cudaGetSymbolAddress((void**)&bta,   g_b_ta);

    cudaFuncSetAttribute(mma_pool,
        cudaFuncAttributeMaxDynamicSharedMemorySize, SMEM_BYTES);

    const int M = M_ROWS;

    // ---- P1: fused prepass ----
    {
        int total = 3 * (M * 128) + M * 16 + M * 2 + M * 32;
        prepass_main<<<(total + 255) / 256, 256>>>(
            gvec, xnode, znode, atom_onehot, bond_onehot, src_graph_vecs,
            batch_idx, gvh, xnh, znh, aohh, bohh, ctxh);
    }
    // ---- P2: batched transposes ----
    {
        TD tT = {topo_w1, wtTA,                       1152, 1152, 512, 576, 36};
        TD tA = {atom_w1, wtTA + (size_t)512 * 1152,  1152, 1152, 512, 576, 36};
        TD tB = {bond_w1, wtB,                        1664, 1664, 512, 832, 52};
        TD tR = {rbond_w, wtR,                        576,  576,  512, 288, 18};
        TD tW = {wbond_w, wtW,                        516,  576,  512, 288, 18};
        dim3 tb(32, 8);
        transpose_all<<<576 + 576 + 832 + 288 + 288, tb>>>(tT, tA, tB, tR, tW);
    }
    // ---- P3: W2 assembly ----
    build_w2t<<<(128 * 1536 + 255) / 256, 256>>>(topo_w2, topo_b2, atom_w2, atom_b2,
                                                 bond_w2, bond_b2, topo_b1, atom_b1);

    // ---- GEMM descriptors ----
    GemmDesc K1 = {{{{znh, 512}, {bohh, 8}, {nullptr, 0}, {nullptr, 0}}},
                   wtW, wbond_b, histh, 576, 512, 512, 9, 4, 0, 1, 1};
    GemmDesc K2 = {{{{histh, 512}, {aohh, 64}, {nullptr, 0}, {nullptr, 0}}},
                   wtR, rbond_b, curh, 576, 512, 512, 9, 4, 0, 1, 1};
    GemmDesc K5 = {{{{gvh, 512}, {curh, 512}, {znh, 512}, {ctxh, 128}}},
                   wtB, bond_b1, hbh, 1664, 512, 512, 26, 4, 0, 1, 1};
    GemmDesc K6 = {{{{htah, 1024}, {hbh, 512}, {nullptr, 0}, {nullptr, 0}}},
                   w2t, b2, out, 1536, 69, 69, 24, 1, 0, 0, 0};
    GemmDesc KF0 = {{{{gvh, 512}, {xnh, 512}, {ctxh, 128}, {nullptr, 0}}},
                    wtTA, bta, htah, 1152, 1024, 1024, 18, 8, 0, 1, 1};
    GemmDesc KF1 = KF0; KF1.my0 = 86;
    GemmDesc KF2 = KF0; KF2.my0 = 171;
    // slice row counts: 86, 85, 85  (sum 256)

    const dim3 blk(256);

    // Phase A: K1 (1024 CTAs) + KF slice0 (86*8 = 688)
    mma_pool<<<1024 + 688, blk, SMEM_BYTES>>>(K1, KF0, 1024);
    // Phase B: K2 (1024) + KF slice1 (85*8 = 680)
    mma_pool<<<1024 + 680, blk, SMEM_BYTES>>>(K2, KF1, 1024);
    // Phase C: K5 (1024) + KF slice2 (85*8 = 680)
    mma_pool<<<1024 + 680, blk, SMEM_BYTES>>>(K5, KF2, 1024);
    // Phase D: K6 (256)
    mma_pool<<<256, blk, SMEM_BYTES>>>(K6, K6, 256);
}

// round 10
// speedup vs baseline: 1.0057x; 1.0057x over previous
#include <cuda_runtime.h>
#include <cuda_fp16.h>
#include <cstdint>

// ---------------------------------------------------------------------------
// GraphDecoder decode-step — fp16 mma.sync (m16n8k16), ldmatrix + SW128 smem,
// 3-stage cp.async pipeline, wave-pooled scheduling.
// (tcgen05 not compilable under this harness: PTX target compute_103 lacks
//  the 'a' feature set — verified R4.)
//
// Launches:
//   P1: fused prepass (fp16 rounding, ctx gather, boh pad)
//   P2: batched weight transposes (5 matrices -> [N][Kpad] fp16)
//   P3: W2 block-diag assembly + bias concat
//   A : pool( K1 hist=relu([znode|boh8]@wbond)      , KF slice 0 )
//   B : pool( K2 cur =relu([hist|aoh]@rbond)        , KF slice 1 )
//   C : pool( K5 h_b =relu([gvec|cur|znode|ctx]@bond), KF slice 2 )
//   D : K6 out=[hta|h_b]@W2t+b2  (K=1536, N=69, f32)
//   KF: hta = relu([gvec|xnode|ctx] @ [topo|atom]), K=1152, N=1024
// ---------------------------------------------------------------------------

#define M_ROWS 32768
#define BM 128
#define BN 128
#define BK 64
#define ATILE_B (BM * BK * 2)            // 16384 B
#define STAGE_B (2 * ATILE_B)            // 32768 B
#define NSTAGE 3
#define SMEM_BYTES (NSTAGE * STAGE_B)    // 98304 B

struct SegH { const __half* ptr; int width; };
struct SegsH { SegH s[4]; };

struct GemmDesc {
    SegsH segs;
    const __half* Bt;
    const float*  bias;
    void*         C;
    int ldb, ldc, N, nk, gx, my0, relu, outh;
};

// ----- fp16 scratch -----
__device__ __half g_gvec_h [(size_t)M_ROWS * 512];
__device__ __half g_xnode_h[(size_t)M_ROWS * 512];
__device__ __half g_znode_h[(size_t)M_ROWS * 512];
__device__ __half g_ctx_h  [(size_t)M_ROWS * 128];
__device__ __half g_aoh_h  [(size_t)M_ROWS * 64];
__device__ __half g_boh_h  [(size_t)M_ROWS * 8];
__device__ __half g_hist_h [(size_t)M_ROWS * 512];
__device__ __half g_cur_h  [(size_t)M_ROWS * 512];
__device__ __half g_hta_h  [(size_t)M_ROWS * 1024];
__device__ __half g_hb_h   [(size_t)M_ROWS * 512];
__device__ __half g_wt_ta   [1024 * 1152];
__device__ __half g_wt_bond [512 * 1664];
__device__ __half g_wt_rbond[512 * 576];
__device__ __half g_wt_wbond[512 * 576];
__device__ __half g_w2t     [128 * 1536];
__device__ float  g_b_ta[1024];
__device__ float  g_b2[72];

// ---------------------------------------------------------------------------
// P1: fused prepass — gvec | xnode | znode | aoh | boh-pad | ctx-gather
// ---------------------------------------------------------------------------
__global__ void prepass_main(const float* __restrict__ gvec,
                             const float* __restrict__ xnode,
                             const float* __restrict__ znode,
                             const float* __restrict__ aoh,
                             const float* __restrict__ boh,
                             const float* __restrict__ src,
                             const int* __restrict__ idx,
                             __half* __restrict__ gvh, __half* __restrict__ xnh,
                             __half* __restrict__ znh, __half* __restrict__ aohh,
                             __half* __restrict__ bohh, __half* __restrict__ ctxh)
{
    const int n512 = M_ROWS * 128;
    const int nA   = M_ROWS * 16;
    const int nB   = M_ROWS * 2;
    const int nC   = M_ROWS * 32;
    int i = blockIdx.x * blockDim.x + threadIdx.x;
    if (i >= 3 * n512 + nA + nB + nC) return;

    const float* in;
    __half* out;
    int j;
    if (i < n512)               { in = gvec;  out = gvh;  j = i; }
    else if (i < 2 * n512)      { in = xnode; out = xnh;  j = i - n512; }
    else if (i < 3 * n512)      { in = znode; out = znh;  j = i - 2 * n512; }
    else if (i < 3 * n512 + nA) { in = aoh;   out = aohh; j = i - 3 * n512; }
    else if (i < 3 * n512 + nA + nB) {
        j = i - 3 * n512 - nA;
        int m = j >> 1, g = j & 1;
        __half2 h0, h1;
        if (g == 0) {
            float4 v = *reinterpret_cast<const float4*>(boh + (size_t)m * 4);
            h0 = __floats2half2_rn(v.x, v.y);
            h1 = __floats2half2_rn(v.z, v.w);
        } else {
            h0 = __floats2half2_rn(0.f, 0.f);
            h1 = h0;
        }
        __half* o = bohh + (size_t)m * 8 + g * 4;
        *reinterpret_cast<__half2*>(o)     = h0;
        *reinterpret_cast<__half2*>(o + 2) = h1;
        return;
    } else {
        j = i - 3 * n512 - nA - nB;
        int m = j >> 5;
        int c = (j & 31) * 4;
        float4 v = *reinterpret_cast<const float4*>(src + (size_t)idx[m] * 128 + c);
        __half* o = ctxh + (size_t)m * 128 + c;
        *reinterpret_cast<__half2*>(o)     = __floats2half2_rn(v.x, v.y);
        *reinterpret_cast<__half2*>(o + 2) = __floats2half2_rn(v.z, v.w);
        return;
    }
    float4 v = *reinterpret_cast<const float4*>(in + (size_t)j * 4);
    *reinterpret_cast<__half2*>(out + (size_t)j * 4)     = __floats2half2_rn(v.x, v.y);
    *reinterpret_cast<__half2*>(out + (size_t)j * 4 + 2) = __floats2half2_rn(v.z, v.w);
}

// ---------------------------------------------------------------------------
// P2: batched transposes.  w [Kin][N] f32 -> wt [N][Kpad] fp16.
// ---------------------------------------------------------------------------
struct TD { const float* w; __half* wt; int Kin, Kpad, N, tiles, kTiles; };

__global__ void transpose_all(TD t0, TD t1, TD t2, TD t3, TD t4)
{
    __shared__ float t[32][33];
    int id = blockIdx.x;
    TD td;
    if (id < t0.tiles) td = t0;
    else { id -= t0.tiles;
    if (id < t1.tiles) td = t1;
    else { id -= t1.tiles;
    if (id < t2.tiles) td = t2;
    else { id -= t2.tiles;
    if (id < t3.tiles) td = t3;
    else { id -= t3.tiles; td = t4; } } } }

    int kb = (id % td.kTiles) * 32;
    int nb = (id / td.kTiles) * 32;
    int x = threadIdx.x, y = threadIdx.y;  // (32, 8)
#pragma unroll
    for (int dy = 0; dy < 32; dy += 8) {
        int k = kb + y + dy, n = nb + x;
        t[y + dy][x] = (k < td.Kin && n < td.N) ? td.w[(size_t)k * td.N + n] : 0.0f;
    }
    __syncthreads();
#pragma unroll
    for (int dy = 0; dy < 32; dy += 8) {
        int n = nb + y + dy, k = kb + x;
        if (n < td.N && k < td.Kpad)
            td.wt[(size_t)n * td.Kpad + k] = __float2half_rn(t[x][y + dy]);
    }
}

// ---------------------------------------------------------------------------
// P3: W2 block-diag [128 x 1536] + biases
// ---------------------------------------------------------------------------
__global__ void build_w2t(const float* __restrict__ tw2, const float* __restrict__ tb2,
                          const float* __restrict__ aw2, const float* __restrict__ ab2,
                          const float* __restrict__ bw2, const float* __restrict__ bb2,
                          const float* __restrict__ tb1, const float* __restrict__ ab1)
{
    int i = blockIdx.x * blockDim.x + threadIdx.x;
    if (i < 128 * 1536) {
        int n = i / 1536, k = i - n * 1536;
        float v = 0.0f;
        if (n == 0) {
            if (k < 512) v = tw2[k];
        } else if (n < 65) {
            if (k >= 512 && k < 1024) v = aw2[(k - 512) * 64 + (n - 1)];
        } else if (n < 69) {
            if (k >= 1024) v = bw2[(k - 1024) * 4 + (n - 65)];
        }
        g_w2t[i] = __float2half_rn(v);
    }
    if (i < 72) {
        float b = 0.0f;
        if (i == 0)      b = tb2[0];
        else if (i < 65) b = ab2[i - 1];
        else if (i < 69) b = bb2[i - 65];
        g_b2[i] = b;
    }
    if (i < 1024) g_b_ta[i] = (i < 512) ? tb1[i] : ab1[i - 512];
}

// ---------------------------------------------------------------------------
__device__ __forceinline__ void cp_async16(uint32_t smem_dst, const void* gsrc, int src_bytes)
{
    asm volatile("cp.async.cg.shared.global [%0], [%1], 16, %2;\n"
                 :: "r"(smem_dst), "l"(gsrc), "r"(src_bytes));
}
__device__ __forceinline__ void mma_f16(float* c, const uint32_t* a, const uint32_t* b)
{
    asm volatile(
        "mma.sync.aligned.m16n8k16.row.col.f32.f16.f16.f32 "
        "{%0,%1,%2,%3}, {%4,%5,%6,%7}, {%8,%9}, {%0,%1,%2,%3};"
        : "+f"(c[0]), "+f"(c[1]), "+f"(c[2]), "+f"(c[3])
        : "r"(a[0]), "r"(a[1]), "r"(a[2]), "r"(a[3]), "r"(b[0]), "r"(b[1]));
}
__device__ __forceinline__ void ldsm_x4(uint32_t& r0, uint32_t& r1, uint32_t& r2,
                                        uint32_t& r3, uint32_t addr)
{
    asm volatile("ldmatrix.sync.aligned.m8n8.x4.shared.b16 {%0,%1,%2,%3}, [%4];"
                 : "=r"(r0), "=r"(r1), "=r"(r2), "=r"(r3) : "r"(addr));
}
__device__ __forceinline__ uint32_t swz(uint32_t row, uint32_t kbyte)
{
    return row * 128u + (kbyte ^ ((row & 7u) * 16u));
}

// ---------------------------------------------------------------------------
// Pooled segmented-A fp16 GEMM: two problems per launch, selected by CTA id.
// ---------------------------------------------------------------------------
__global__ __launch_bounds__(256, 2)
void mma_pool(GemmDesc d0, GemmDesc d1, int n0)
{
    extern __shared__ char sm[];
    const uint32_t sbase = (uint32_t)__cvta_generic_to_shared(sm);

    const bool first = ((int)blockIdx.x < n0);
    GemmDesc d = first ? d0 : d1;
    const int local = (int)blockIdx.x - (first ? 0 : n0);

    const int bn = (local % d.gx) * BN;
    const int bm = (local / d.gx + d.my0) * BM;

    const int tid  = threadIdx.x;
    const int lane = tid & 31;
    const int warp = tid >> 5;
    const int wm   = warp >> 2;
    const int wn   = warp & 3;

    const int arow = tid >> 3;
    const int ac8  = tid & 7;

    const int nk = d.nk;
    const bool wact = (bn + wn * 32) < ((d.N + 7) & ~7);

    const uint32_t a_row_l = (lane & 7) + ((lane >> 3) & 1) * 8;
    const uint32_t a_kx    = ((lane >> 4) & 1) * 16;
    const uint32_t b_row_l = (lane & 7) + ((lane >> 4) & 1) * 8;
    const uint32_t b_kx    = ((lane >> 3) & 1) * 16;

    float acc[4][4][4];
#pragma unroll
    for (int mt = 0; mt < 4; ++mt)
#pragma unroll
        for (int nt = 0; nt < 4; ++nt)
#pragma unroll
            for (int i = 0; i < 4; ++i) acc[mt][nt][i] = 0.0f;

    auto load_tile = [&](int kt, int buf) {
        const uint32_t Aoff = sbase + buf * STAGE_B;
        const uint32_t Boff = Aoff + ATILE_B;
        const int k0 = kt * BK;
        const int col = k0 + ac8 * 8;
        const __half* sptr = nullptr;
        int swid = 0, cloc = 0;
        bool valid = false;
        int cc = col;
#pragma unroll
        for (int s = 0; s < 4; ++s) {
            if (cc >= 0 && cc < d.segs.s[s].width) {
                sptr = d.segs.s[s].ptr; swid = d.segs.s[s].width;
                cloc = cc; valid = true;
            }
            cc -= d.segs.s[s].width;
        }
#pragma unroll
        for (int p = 0; p < 4; ++p) {
            const uint32_t row = arow + 32 * p;
            const void* src = valid
                ? (const void*)(sptr + (size_t)(bm + row) * swid + cloc)
                : (const void*)d.bias;
            cp_async16(Aoff + swz(row, ac8 * 16), src, valid ? 16 : 0);
        }
#pragma unroll
        for (int p = 0; p < 4; ++p) {
            const uint32_t row = arow + 32 * p;
            const void* src = d.Bt + (size_t)(bn + row) * d.ldb + k0 + ac8 * 8;
            cp_async16(Boff + swz(row, ac8 * 16), src, 16);
        }
        asm volatile("cp.async.commit_group;\n" ::);
    };

    load_tile(0, 0);
    if (nk > 1) load_tile(1, 1);

    for (int kt = 0; kt < nk; ++kt) {
        const int buf = kt % NSTAGE;
        if (kt + 2 < nk) {
            load_tile(kt + 2, (kt + 2) % NSTAGE);
            asm volatile("cp.async.wait_group 2;\n" ::);
        } else if (kt + 1 < nk) {
            asm volatile("cp.async.wait_group 1;\n" ::);
        } else {
            asm volatile("cp.async.wait_group 0;\n" ::);
        }
        __syncthreads();

        const uint32_t Aoff = sbase + buf * STAGE_B;
        const uint32_t Boff = Aoff + ATILE_B;

        if (wact) {
#pragma unroll
            for (int s = 0; s < BK / 16; ++s) {
                const uint32_t ka = s * 32 + a_kx;
                const uint32_t kb = s * 32 + b_kx;
                uint32_t a[4][4], b[2][4];
#pragma unroll
                for (int mt = 0; mt < 4; ++mt) {
                    const uint32_t row = wm * 64 + mt * 16 + a_row_l;
                    ldsm_x4(a[mt][0], a[mt][1], a[mt][2], a[mt][3], Aoff + swz(row, ka));
                }
#pragma unroll
                for (int np = 0; np < 2; ++np) {
                    const uint32_t row = wn * 32 + np * 16 + b_row_l;
                    ldsm_x4(b[np][0], b[np][1], b[np][2], b[np][3], Boff + swz(row, kb));
                }
#pragma unroll
                for (int mt = 0; mt < 4; ++mt)
#pragma unroll
                    for (int nt = 0; nt < 4; ++nt)
                        mma_f16(acc[mt][nt], a[mt], &b[nt >> 1][(nt & 1) * 2]);
            }
        }
        __syncthreads();
    }

    // ---- epilogue ----
#pragma unroll
    for (int mt = 0; mt < 4; ++mt) {
        const int r0 = bm + wm * 64 + mt * 16 + (lane >> 2);
#pragma unroll
        for (int nt = 0; nt < 4; ++nt) {
            const int c0 = bn + wn * 32 + nt * 8 + (lane & 3) * 2;
            float bv0 = (c0     < d.N) ? d.bias[c0]     : 0.0f;
            float bv1 = (c0 + 1 < d.N) ? d.bias[c0 + 1] : 0.0f;
            float v00 = acc[mt][nt][0] + bv0;
            float v01 = acc[mt][nt][1] + bv1;
            float v10 = acc[mt][nt][2] + bv0;
            float v11 = acc[mt][nt][3] + bv1;
            if (d.relu) {
                v00 = fmaxf(v00, 0.0f); v01 = fmaxf(v01, 0.0f);
                v10 = fmaxf(v10, 0.0f); v11 = fmaxf(v11, 0.0f);
            }
            if (d.outh) {
                __half* C = (__half*)d.C;
                *reinterpret_cast<__half2*>(C + (size_t)r0 * d.ldc + c0)
                    = __floats2half2_rn(v00, v01);
                *reinterpret_cast<__half2*>(C + (size_t)(r0 + 8) * d.ldc + c0)
                    = __floats2half2_rn(v10, v11);
            } else {
                float* C = (float*)d.C;
                if (c0 < d.N) {
                    C[(size_t)r0 * d.ldc + c0]       = v00;
                    C[(size_t)(r0 + 8) * d.ldc + c0] = v10;
                }
                if (c0 + 1 < d.N) {
                    C[(size_t)r0 * d.ldc + c0 + 1]       = v01;
                    C[(size_t)(r0 + 8) * d.ldc + c0 + 1] = v11;
                }
            }
        }
    }
}

// ---------------------------------------------------------------------------
extern "C" void kernel_launch(void* const* d_in, const int* in_sizes, int n_in,
                              void* d_out, int out_size)
{
    (void)in_sizes; (void)n_in; (void)out_size;

    const float* src_graph_vecs = (const float*)d_in[0];
    const float* gvec           = (const float*)d_in[1];
    const float* xnode          = (const float*)d_in[2];
    const float* znode          = (const float*)d_in[3];
    const float* atom_onehot    = (const float*)d_in[4];
    const float* bond_onehot    = (const float*)d_in[5];
    const float* topo_w1        = (const float*)d_in[6];
    const float* topo_b1        = (const float*)d_in[7];
    const float* topo_w2        = (const float*)d_in[8];
    const float* topo_b2        = (const float*)d_in[9];
    const float* atom_w1        = (const float*)d_in[10];
    const float* atom_b1        = (const float*)d_in[11];
    const float* atom_w2        = (const float*)d_in[12];
    const float* atom_b2        = (const float*)d_in[13];
    const float* bond_w1        = (const float*)d_in[14];
    const float* bond_b1        = (const float*)d_in[15];
    const float* bond_w2        = (const float*)d_in[16];
    const float* bond_b2        = (const float*)d_in[17];
    const float* rbond_w        = (const float*)d_in[18];
    const float* rbond_b        = (const float*)d_in[19];
    const float* wbond_w        = (const float*)d_in[20];
    const float* wbond_b        = (const float*)d_in[21];
    const int*   batch_idx      = (const int*)d_in[22];
    float*       out            = (float*)d_out;

    __half *gvh, *xnh, *znh, *ctxh, *aohh, *bohh;
    __half *histh, *curh, *htah, *hbh;
    __half *wtTA, *wtB, *wtR, *wtW, *w2t;
    float  *b2, *bta;
    cudaGetSymbolAddress((void**)&gvh,   g_gvec_h);
    cudaGetSymbolAddress((void**)&xnh,   g_xnode_h);
    cudaGetSymbolAddress((void**)&znh,   g_znode_h);
    cudaGetSymbolAddress((void**)&ctxh,  g_ctx_h);
    cudaGetSymbolAddress((void**)&aohh,  g_aoh_h);
    cudaGetSymbolAddress((void**)&bohh,  g_boh_h);
    cudaGetSymbolAddress((void**)&histh, g_hist_h);
    cudaGetSymbolAddress((void**)&curh,  g_cur_h);
    cudaGetSymbolAddress((void**)&htah,  g_hta_h);
    cudaGetSymbolAddress((void**)&hbh,   g_hb_h);
    cudaGetSymbolAddress((void**)&wtTA,  g_wt_ta);
    cudaGetSymbolAddress((void**)&wtB,   g_wt_bond);
    cudaGetSymbolAddress((void**)&wtR,   g_wt_rbond);
    cudaGetSymbolAddress((void**)&wtW,   g_wt_wbond);
    cudaGetSymbolAddress((void**)&w2t,   g_w2t);
    cudaGetSymbolAddress((void**)&b2,    g_b2);
    cudaGetSymbolAddress((void**)&bta,   g_b_ta);

    cudaFuncSetAttribute(mma_pool,
        cudaFuncAttributeMaxDynamicSharedMemorySize, SMEM_BYTES);

    const int M = M_ROWS;

    // ---- P1: fused prepass ----
    {
        int total = 3 * (M * 128) + M * 16 + M * 2 + M * 32;
        prepass_main<<<(total + 255) / 256, 256>>>(
            gvec, xnode, znode, atom_onehot, bond_onehot, src_graph_vecs,
            batch_idx, gvh, xnh, znh, aohh, bohh, ctxh);
    }
    // ---- P2: batched transposes ----
    {
        TD tT = {topo_w1, wtTA,                       1152, 1152, 512, 576, 36};
        TD tA = {atom_w1, wtTA + (size_t)512 * 1152,  1152, 1152, 512, 576, 36};
        TD tB = {bond_w1, wtB,                        1664, 1664, 512, 832, 52};
        TD tR = {rbond_w, wtR,                        576,  576,  512, 288, 18};
        TD tW = {wbond_w, wtW,                        516,  576,  512, 288, 18};
        dim3 tb(32, 8);
        transpose_all<<<576 + 576 + 832 + 288 + 288, tb>>>(tT, tA, tB, tR, tW);
    }
    // ---- P3: W2 assembly ----
    build_w2t<<<(128 * 1536 + 255) / 256, 256>>>(topo_w2, topo_b2, atom_w2, atom_b2,
                                                 bond_w2, bond_b2, topo_b1, atom_b1);

    // ---- GEMM descriptors ----
    GemmDesc K1 = {{{{znh, 512}, {bohh, 8}, {nullptr, 0}, {nullptr, 0}}},
                   wtW, wbond_b, histh, 576, 512, 512, 9, 4, 0, 1, 1};
    GemmDesc K2 = {{{{histh, 512}, {aohh, 64}, {nullptr, 0}, {nullptr, 0}}},
                   wtR, rbond_b, curh, 576, 512, 512, 9, 4, 0, 1, 1};
    GemmDesc K5 = {{{{gvh, 512}, {curh, 512}, {znh, 512}, {ctxh, 128}}},
                   wtB, bond_b1, hbh, 1664, 512, 512, 26, 4, 0, 1, 1};
    GemmDesc K6 = {{{{htah, 1024}, {hbh, 512}, {nullptr, 0}, {nullptr, 0}}},
                   w2t, b2, out, 1536, 69, 69, 24, 1, 0, 0, 0};
    GemmDesc KF0 = {{{{gvh, 512}, {xnh, 512}, {ctxh, 128}, {nullptr, 0}}},
                    wtTA, bta, htah, 1152, 1024, 1024, 18, 8, 0, 1, 1};
    GemmDesc KF1 = KF0; KF1.my0 = 86;
    GemmDesc KF2 = KF0; KF2.my0 = 171;
    // slice row counts: 86, 85, 85  (sum 256)

    const dim3 blk(256);

    // Phase A: K1 (1024 CTAs) + KF slice0 (86*8 = 688)
    mma_pool<<<1024 + 688, blk, SMEM_BYTES>>>(K1, KF0, 1024);
    // Phase B: K2 (1024) + KF slice1 (85*8 = 680)
    mma_pool<<<1024 + 680, blk, SMEM_BYTES>>>(K2, KF1, 1024);
    // Phase C: K5 (1024) + KF slice2 (85*8 = 680)
    mma_pool<<<1024 + 680, blk, SMEM_BYTES>>>(K5, KF2, 1024);
    // Phase D: K6 (256)
    mma_pool<<<256, blk, SMEM_BYTES>>>(K6, K6, 256);
}

// round 11
// speedup vs baseline: 1.0597x; 1.0537x over previous
#include <cuda_runtime.h>
#include <cuda_fp16.h>
#include <cstdint>

// ---------------------------------------------------------------------------
// GraphDecoder decode-step — fp16 mma.sync (m16n8k16), ldmatrix + SW128 smem,
// 3-stage cp.async pipeline, fragment double-buffering.
// (tcgen05 not compilable under this harness — verified R4.)
//
//   P1: fused prepass (fp16 rounding, ctx gather, boh pad)
//   P2: batched weight transposes
//   P3: W2 block-diag assembly + bias concat
//   K1: hist = relu([znode|boh8] @ wbond)            Kpad=576
//   KF: hta  = relu([gvec|xnode|ctx] @ [topo|atom])  K=1152, N=1024
//   K2: cur  = relu([hist|aoh] @ rbond)              K=576
//   K5: h_b  = relu([gvec|cur|znode|ctx] @ bond)     K=1664
//   K6: out  = [hta|h_b] @ W2t + b2                  K=1536, N=69 (f32)
// ---------------------------------------------------------------------------

#define M_ROWS 32768
#define BM 128
#define BN 128
#define BK 64
#define ATILE_B (BM * BK * 2)            // 16384 B
#define STAGE_B (2 * ATILE_B)            // 32768 B
#define NSTAGE 3
#define SMEM_BYTES (NSTAGE * STAGE_B)    // 98304 B

struct SegH { const __half* ptr; int width; };
struct SegsH { SegH s[4]; };

// ----- fp16 scratch -----
__device__ __half g_gvec_h [(size_t)M_ROWS * 512];
__device__ __half g_xnode_h[(size_t)M_ROWS * 512];
__device__ __half g_znode_h[(size_t)M_ROWS * 512];
__device__ __half g_ctx_h  [(size_t)M_ROWS * 128];
__device__ __half g_aoh_h  [(size_t)M_ROWS * 64];
__device__ __half g_boh_h  [(size_t)M_ROWS * 8];
__device__ __half g_hist_h [(size_t)M_ROWS * 512];
__device__ __half g_cur_h  [(size_t)M_ROWS * 512];
__device__ __half g_hta_h  [(size_t)M_ROWS * 1024];
__device__ __half g_hb_h   [(size_t)M_ROWS * 512];
__device__ __half g_wt_ta   [1024 * 1152];
__device__ __half g_wt_bond [512 * 1664];
__device__ __half g_wt_rbond[512 * 576];
__device__ __half g_wt_wbond[512 * 576];
__device__ __half g_w2t     [128 * 1536];
__device__ float  g_b_ta[1024];
__device__ float  g_b2[72];

// ---------------------------------------------------------------------------
// P1: fused prepass — gvec | xnode | znode | aoh | boh-pad | ctx-gather
// ---------------------------------------------------------------------------
__global__ void prepass_main(const float* __restrict__ gvec,
                             const float* __restrict__ xnode,
                             const float* __restrict__ znode,
                             const float* __restrict__ aoh,
                             const float* __restrict__ boh,
                             const float* __restrict__ src,
                             const int* __restrict__ idx,
                             __half* __restrict__ gvh, __half* __restrict__ xnh,
                             __half* __restrict__ znh, __half* __restrict__ aohh,
                             __half* __restrict__ bohh, __half* __restrict__ ctxh)
{
    const int n512 = M_ROWS * 128;
    const int nA   = M_ROWS * 16;
    const int nB   = M_ROWS * 2;
    const int nC   = M_ROWS * 32;
    int i = blockIdx.x * blockDim.x + threadIdx.x;
    if (i >= 3 * n512 + nA + nB + nC) return;

    const float* in;
    __half* out;
    int j;
    if (i < n512)               { in = gvec;  out = gvh;  j = i; }
    else if (i < 2 * n512)      { in = xnode; out = xnh;  j = i - n512; }
    else if (i < 3 * n512)      { in = znode; out = znh;  j = i - 2 * n512; }
    else if (i < 3 * n512 + nA) { in = aoh;   out = aohh; j = i - 3 * n512; }
    else if (i < 3 * n512 + nA + nB) {
        j = i - 3 * n512 - nA;
        int m = j >> 1, g = j & 1;
        __half2 h0, h1;
        if (g == 0) {
            float4 v = *reinterpret_cast<const float4*>(boh + (size_t)m * 4);
            h0 = __floats2half2_rn(v.x, v.y);
            h1 = __floats2half2_rn(v.z, v.w);
        } else {
            h0 = __floats2half2_rn(0.f, 0.f);
            h1 = h0;
        }
        __half* o = bohh + (size_t)m * 8 + g * 4;
        *reinterpret_cast<__half2*>(o)     = h0;
        *reinterpret_cast<__half2*>(o + 2) = h1;
        return;
    } else {
        j = i - 3 * n512 - nA - nB;
        int m = j >> 5;
        int c = (j & 31) * 4;
        float4 v = *reinterpret_cast<const float4*>(src + (size_t)idx[m] * 128 + c);
        __half* o = ctxh + (size_t)m * 128 + c;
        *reinterpret_cast<__half2*>(o)     = __floats2half2_rn(v.x, v.y);
        *reinterpret_cast<__half2*>(o + 2) = __floats2half2_rn(v.z, v.w);
        return;
    }
    float4 v = *reinterpret_cast<const float4*>(in + (size_t)j * 4);
    *reinterpret_cast<__half2*>(out + (size_t)j * 4)     = __floats2half2_rn(v.x, v.y);
    *reinterpret_cast<__half2*>(out + (size_t)j * 4 + 2) = __floats2half2_rn(v.z, v.w);
}

// ---------------------------------------------------------------------------
// P2: batched transposes.  w [Kin][N] f32 -> wt [N][Kpad] fp16.
// ---------------------------------------------------------------------------
struct TD { const float* w; __half* wt; int Kin, Kpad, N, tiles, kTiles; };

__global__ void transpose_all(TD t0, TD t1, TD t2, TD t3, TD t4)
{
    __shared__ float t[32][33];
    int id = blockIdx.x;
    TD td;
    if (id < t0.tiles) td = t0;
    else { id -= t0.tiles;
    if (id < t1.tiles) td = t1;
    else { id -= t1.tiles;
    if (id < t2.tiles) td = t2;
    else { id -= t2.tiles;
    if (id < t3.tiles) td = t3;
    else { id -= t3.tiles; td = t4; } } } }

    int kb = (id % td.kTiles) * 32;
    int nb = (id / td.kTiles) * 32;
    int x = threadIdx.x, y = threadIdx.y;  // (32, 8)
#pragma unroll
    for (int dy = 0; dy < 32; dy += 8) {
        int k = kb + y + dy, n = nb + x;
        t[y + dy][x] = (k < td.Kin && n < td.N) ? td.w[(size_t)k * td.N + n] : 0.0f;
    }
    __syncthreads();
#pragma unroll
    for (int dy = 0; dy < 32; dy += 8) {
        int n = nb + y + dy, k = kb + x;
        if (n < td.N && k < td.Kpad)
            td.wt[(size_t)n * td.Kpad + k] = __float2half_rn(t[x][y + dy]);
    }
}

// ---------------------------------------------------------------------------
// P3: W2 block-diag [128 x 1536] + biases
// ---------------------------------------------------------------------------
__global__ void build_w2t(const float* __restrict__ tw2, const float* __restrict__ tb2,
                          const float* __restrict__ aw2, const float* __restrict__ ab2,
                          const float* __restrict__ bw2, const float* __restrict__ bb2,
                          const float* __restrict__ tb1, const float* __restrict__ ab1)
{
    int i = blockIdx.x * blockDim.x + threadIdx.x;
    if (i < 128 * 1536) {
        int n = i / 1536, k = i - n * 1536;
        float v = 0.0f;
        if (n == 0) {
            if (k < 512) v = tw2[k];
        } else if (n < 65) {
            if (k >= 512 && k < 1024) v = aw2[(k - 512) * 64 + (n - 1)];
        } else if (n < 69) {
            if (k >= 1024) v = bw2[(k - 1024) * 4 + (n - 65)];
        }
        g_w2t[i] = __float2half_rn(v);
    }
    if (i < 72) {
        float b = 0.0f;
        if (i == 0)      b = tb2[0];
        else if (i < 65) b = ab2[i - 1];
        else if (i < 69) b = bb2[i - 65];
        g_b2[i] = b;
    }
    if (i < 1024) g_b_ta[i] = (i < 512) ? tb1[i] : ab1[i - 512];
}

// ---------------------------------------------------------------------------
__device__ __forceinline__ void cp_async16(uint32_t smem_dst, const void* gsrc, int src_bytes)
{
    asm volatile("cp.async.cg.shared.global [%0], [%1], 16, %2;\n"
                 :: "r"(smem_dst), "l"(gsrc), "r"(src_bytes));
}
__device__ __forceinline__ void mma_f16(float* c, const uint32_t* a, const uint32_t* b)
{
    asm volatile(
        "mma.sync.aligned.m16n8k16.row.col.f32.f16.f16.f32 "
        "{%0,%1,%2,%3}, {%4,%5,%6,%7}, {%8,%9}, {%0,%1,%2,%3};"
        : "+f"(c[0]), "+f"(c[1]), "+f"(c[2]), "+f"(c[3])
        : "r"(a[0]), "r"(a[1]), "r"(a[2]), "r"(a[3]), "r"(b[0]), "r"(b[1]));
}
__device__ __forceinline__ void ldsm_x4(uint32_t& r0, uint32_t& r1, uint32_t& r2,
                                        uint32_t& r3, uint32_t addr)
{
    asm volatile("ldmatrix.sync.aligned.m8n8.x4.shared.b16 {%0,%1,%2,%3}, [%4];"
                 : "=r"(r0), "=r"(r1), "=r"(r2), "=r"(r3) : "r"(addr));
}
__device__ __forceinline__ uint32_t swz(uint32_t row, uint32_t kbyte)
{
    return row * 128u + (kbyte ^ ((row & 7u) * 16u));
}

// ---------------------------------------------------------------------------
// Segmented-A fp16 GEMM with fragment double-buffering.
// ---------------------------------------------------------------------------
template <int NSEG, bool RELU, bool OUTH>
__global__ __launch_bounds__(256, 2)
void mma_h(int N, int Kpad, SegsH segs,
           const __half* __restrict__ Bt, int ldb,
           const float* __restrict__ bias,
           void* __restrict__ Cv, int ldc)
{
    extern __shared__ char sm[];
    const uint32_t sbase = (uint32_t)__cvta_generic_to_shared(sm);

    const int bn   = blockIdx.x * BN;
    const int bm   = blockIdx.y * BM;
    const int tid  = threadIdx.x;
    const int lane = tid & 31;
    const int warp = tid >> 5;
    const int wm   = warp >> 2;
    const int wn   = warp & 3;

    const int arow = tid >> 3;
    const int ac8  = tid & 7;

    const int nk = Kpad / BK;
    const bool wact = (bn + wn * 32) < ((N + 7) & ~7);

    const uint32_t a_row_l = (lane & 7) + ((lane >> 3) & 1) * 8;
    const uint32_t a_kx    = ((lane >> 4) & 1) * 16;
    const uint32_t b_row_l = (lane & 7) + ((lane >> 4) & 1) * 8;
    const uint32_t b_kx    = ((lane >> 3) & 1) * 16;

    float acc[4][4][4];
#pragma unroll
    for (int mt = 0; mt < 4; ++mt)
#pragma unroll
        for (int nt = 0; nt < 4; ++nt)
#pragma unroll
            for (int i = 0; i < 4; ++i) acc[mt][nt][i] = 0.0f;

    auto load_tile = [&](int kt, int buf) {
        const uint32_t Aoff = sbase + buf * STAGE_B;
        const uint32_t Boff = Aoff + ATILE_B;
        const int k0 = kt * BK;
        const int col = k0 + ac8 * 8;
        const __half* sptr = nullptr;
        int swid = 0, cloc = 0;
        bool valid = false;
        int cc = col;
#pragma unroll
        for (int s = 0; s < NSEG; ++s) {
            if (cc >= 0 && cc < segs.s[s].width) {
                sptr = segs.s[s].ptr; swid = segs.s[s].width; cloc = cc; valid = true;
            }
            cc -= segs.s[s].width;
        }
#pragma unroll
        for (int p = 0; p < 4; ++p) {
            const uint32_t row = arow + 32 * p;
            const void* src = valid
                ? (const void*)(sptr + (size_t)(bm + row) * swid + cloc)
                : (const void*)bias;
            cp_async16(Aoff + swz(row, ac8 * 16), src, valid ? 16 : 0);
        }
#pragma unroll
        for (int p = 0; p < 4; ++p) {
            const uint32_t row = arow + 32 * p;
            const void* src = Bt + (size_t)(bn + row) * ldb + k0 + ac8 * 8;
            cp_async16(Boff + swz(row, ac8 * 16), src, 16);
        }
        asm volatile("cp.async.commit_group;\n" ::);
    };

    // fragment registers (double-buffered across k16 steps)
    uint32_t af[2][4][4], bf[2][2][4];

    auto load_frag = [&](int s, int pb, uint32_t Aoff, uint32_t Boff) {
        const uint32_t ka = (uint32_t)s * 32 + a_kx;
        const uint32_t kb = (uint32_t)s * 32 + b_kx;
#pragma unroll
        for (int mt = 0; mt < 4; ++mt) {
            const uint32_t row = wm * 64 + mt * 16 + a_row_l;
            ldsm_x4(af[pb][mt][0], af[pb][mt][1], af[pb][mt][2], af[pb][mt][3],
                    Aoff + swz(row, ka));
        }
#pragma unroll
        for (int np = 0; np < 2; ++np) {
            const uint32_t row = wn * 32 + np * 16 + b_row_l;
            ldsm_x4(bf[pb][np][0], bf[pb][np][1], bf[pb][np][2], bf[pb][np][3],
                    Boff + swz(row, kb));
        }
    };

    // ---- 3-stage pipeline (prefetch-before-wait) ----
    load_tile(0, 0);
    if (nk > 1) load_tile(1, 1);

    for (int kt = 0; kt < nk; ++kt) {
        const int buf = kt % NSTAGE;
        if (kt + 2 < nk) {
            load_tile(kt + 2, (kt + 2) % NSTAGE);
            asm volatile("cp.async.wait_group 2;\n" ::);
        } else if (kt + 1 < nk) {
            asm volatile("cp.async.wait_group 1;\n" ::);
        } else {
            asm volatile("cp.async.wait_group 0;\n" ::);
        }
        __syncthreads();

        const uint32_t Aoff = sbase + buf * STAGE_B;
        const uint32_t Boff = Aoff + ATILE_B;

        if (wact) {
            load_frag(0, 0, Aoff, Boff);
#pragma unroll
            for (int s = 0; s < BK / 16; ++s) {
                if (s + 1 < BK / 16) load_frag(s + 1, (s + 1) & 1, Aoff, Boff);
                const int pb = s & 1;
#pragma unroll
                for (int mt = 0; mt < 4; ++mt)
#pragma unroll
                    for (int nt = 0; nt < 4; ++nt)
                        mma_f16(acc[mt][nt], af[pb][mt], &bf[pb][nt >> 1][(nt & 1) * 2]);
            }
        }
        __syncthreads();
    }

    // ---- epilogue ----
#pragma unroll
    for (int mt = 0; mt < 4; ++mt) {
        const int r0 = bm + wm * 64 + mt * 16 + (lane >> 2);
#pragma unroll
        for (int nt = 0; nt < 4; ++nt) {
            const int c0 = bn + wn * 32 + nt * 8 + (lane & 3) * 2;
            float bv0 = (c0     < N) ? bias[c0]     : 0.0f;
            float bv1 = (c0 + 1 < N) ? bias[c0 + 1] : 0.0f;
            float v00 = acc[mt][nt][0] + bv0;
            float v01 = acc[mt][nt][1] + bv1;
            float v10 = acc[mt][nt][2] + bv0;
            float v11 = acc[mt][nt][3] + bv1;
            if (RELU) {
                v00 = fmaxf(v00, 0.0f); v01 = fmaxf(v01, 0.0f);
                v10 = fmaxf(v10, 0.0f); v11 = fmaxf(v11, 0.0f);
            }
            if (OUTH) {
                __half* C = (__half*)Cv;
                *reinterpret_cast<__half2*>(C + (size_t)r0 * ldc + c0)
                    = __floats2half2_rn(v00, v01);
                *reinterpret_cast<__half2*>(C + (size_t)(r0 + 8) * ldc + c0)
                    = __floats2half2_rn(v10, v11);
            } else {
                float* C = (float*)Cv;
                if (c0 < N) {
                    C[(size_t)r0 * ldc + c0]       = v00;
                    C[(size_t)(r0 + 8) * ldc + c0] = v10;
                }
                if (c0 + 1 < N) {
                    C[(size_t)r0 * ldc + c0 + 1]       = v01;
                    C[(size_t)(r0 + 8) * ldc + c0 + 1] = v11;
                }
            }
        }
    }
}

// ---------------------------------------------------------------------------
extern "C" void kernel_launch(void* const* d_in, const int* in_sizes, int n_in,
                              void* d_out, int out_size)
{
    (void)in_sizes; (void)n_in; (void)out_size;

    const float* src_graph_vecs = (const float*)d_in[0];
    const float* gvec           = (const float*)d_in[1];
    const float* xnode          = (const float*)d_in[2];
    const float* znode          = (const float*)d_in[3];
    const float* atom_onehot    = (const float*)d_in[4];
    const float* bond_onehot    = (const float*)d_in[5];
    const float* topo_w1        = (const float*)d_in[6];
    const float* topo_b1        = (const float*)d_in[7];
    const float* topo_w2        = (const float*)d_in[8];
    const float* topo_b2        = (const float*)d_in[9];
    const float* atom_w1        = (const float*)d_in[10];
    const float* atom_b1        = (const float*)d_in[11];
    const float* atom_w2        = (const float*)d_in[12];
    const float* atom_b2        = (const float*)d_in[13];
    const float* bond_w1        = (const float*)d_in[14];
    const float* bond_b1        = (const float*)d_in[15];
    const float* bond_w2        = (const float*)d_in[16];
    const float* bond_b2        = (const float*)d_in[17];
    const float* rbond_w        = (const float*)d_in[18];
    const float* rbond_b        = (const float*)d_in[19];
    const float* wbond_w        = (const float*)d_in[20];
    const float* wbond_b        = (const float*)d_in[21];
    const int*   batch_idx      = (const int*)d_in[22];
    float*       out            = (float*)d_out;

    __half *gvh, *xnh, *znh, *ctxh, *aohh, *bohh;
    __half *histh, *curh, *htah, *hbh;
    __half *wtTA, *wtB, *wtR, *wtW, *w2t;
    float  *b2, *bta;
    cudaGetSymbolAddress((void**)&gvh,   g_gvec_h);
    cudaGetSymbolAddress((void**)&xnh,   g_xnode_h);
    cudaGetSymbolAddress((void**)&znh,   g_znode_h);
    cudaGetSymbolAddress((void**)&ctxh,  g_ctx_h);
    cudaGetSymbolAddress((void**)&aohh,  g_aoh_h);
    cudaGetSymbolAddress((void**)&bohh,  g_boh_h);
    cudaGetSymbolAddress((void**)&histh, g_hist_h);
    cudaGetSymbolAddress((void**)&curh,  g_cur_h);
    cudaGetSymbolAddress((void**)&htah,  g_hta_h);
    cudaGetSymbolAddress((void**)&hbh,   g_hb_h);
    cudaGetSymbolAddress((void**)&wtTA,  g_wt_ta);
    cudaGetSymbolAddress((void**)&wtB,   g_wt_bond);
    cudaGetSymbolAddress((void**)&wtR,   g_wt_rbond);
    cudaGetSymbolAddress((void**)&wtW,   g_wt_wbond);
    cudaGetSymbolAddress((void**)&w2t,   g_w2t);
    cudaGetSymbolAddress((void**)&b2,    g_b2);
    cudaGetSymbolAddress((void**)&bta,   g_b_ta);

    cudaFuncSetAttribute(mma_h<2, true, true>,
        cudaFuncAttributeMaxDynamicSharedMemorySize, SMEM_BYTES);
    cudaFuncSetAttribute(mma_h<3, true, true>,
        cudaFuncAttributeMaxDynamicSharedMemorySize, SMEM_BYTES);
    cudaFuncSetAttribute(mma_h<4, true, true>,
        cudaFuncAttributeMaxDynamicSharedMemorySize, SMEM_BYTES);
    cudaFuncSetAttribute(mma_h<2, false, false>,
        cudaFuncAttributeMaxDynamicSharedMemorySize, SMEM_BYTES);

    const int M = M_ROWS;

    // ---- P1: fused prepass ----
    {
        int total = 3 * (M * 128) + M * 16 + M * 2 + M * 32;
        prepass_main<<<(total + 255) / 256, 256>>>(
            gvec, xnode, znode, atom_onehot, bond_onehot, src_graph_vecs,
            batch_idx, gvh, xnh, znh, aohh, bohh, ctxh);
    }
    // ---- P2: batched transposes ----
    {
        TD tT = {topo_w1, wtTA,                       1152, 1152, 512, 576, 36};
        TD tA = {atom_w1, wtTA + (size_t)512 * 1152,  1152, 1152, 512, 576, 36};
        TD tB = {bond_w1, wtB,                        1664, 1664, 512, 832, 52};
        TD tR = {rbond_w, wtR,                        576,  576,  512, 288, 18};
        TD tW = {wbond_w, wtW,                        516,  576,  512, 288, 18};
        dim3 tb(32, 8);
        transpose_all<<<576 + 576 + 832 + 288 + 288, tb>>>(tT, tA, tB, tR, tW);
    }
    // ---- P3: W2 assembly ----
    build_w2t<<<(128 * 1536 + 255) / 256, 256>>>(topo_w2, topo_b2, atom_w2, atom_b2,
                                                 bond_w2, bond_b2, topo_b1, atom_b1);

    const dim3 blk(256);
    const dim3 grid512(512 / BN, M / BM);    // (4, 256)
    const dim3 grid1024(1024 / BN, M / BM);  // (8, 256)
    const dim3 grid69(1, M / BM);            // (1, 256)

    // K1: hist = relu([znode | boh8] @ wbond), Kpad=576
    {
        SegsH s; s.s[0] = {znh, 512}; s.s[1] = {bohh, 8};
        s.s[2] = {nullptr, 0}; s.s[3] = {nullptr, 0};
        mma_h<2, true, true><<<grid512, blk, SMEM_BYTES>>>(
            512, 576, s, wtW, 576, wbond_b, histh, 512);
    }
    // KF: hta = relu([gvec | xnode | ctx] @ [topo|atom]), K=1152, N=1024
    {
        SegsH s; s.s[0] = {gvh, 512}; s.s[1] = {xnh, 512};
        s.s[2] = {ctxh, 128}; s.s[3] = {nullptr, 0};
        mma_h<3, true, true><<<grid1024, blk, SMEM_BYTES>>>(
            1024, 1152, s, wtTA, 1152, bta, htah, 1024);
    }
    // K2: cur = relu([hist | aoh] @ rbond), K=576
    {
        SegsH s; s.s[0] = {histh, 512}; s.s[1] = {aohh, 64};
        s.s[2] = {nullptr, 0}; s.s[3] = {nullptr, 0};
        mma_h<2, true, true><<<grid512, blk, SMEM_BYTES>>>(
            512, 576, s, wtR, 576, rbond_b, curh, 512);
    }
    // K5: h_b = relu([gvec | cur | znode | ctx] @ bond), K=1664
    {
        SegsH s; s.s[0] = {gvh, 512}; s.s[1] = {curh, 512};
        s.s[2] = {znh, 512}; s.s[3] = {ctxh, 128};
        mma_h<4, true, true><<<grid512, blk, SMEM_BYTES>>>(
            512, 1664, s, wtB, 1664, bond_b1, hbh, 512);
    }
    // K6: out = [hta | h_b] @ W2t + b2, K=1536, N=69 (f32); wn=3 warps idle
    {
        SegsH s; s.s[0] = {htah, 1024}; s.s[1] = {hbh, 512};
        s.s[2] = {nullptr, 0}; s.s[3] = {nullptr, 0};
        mma_h<2, false, false><<<grid69, blk, SMEM_BYTES>>>(
            69, 1536, s, w2t, 1536, b2, out, 69);
    }
}